// round 4
// baseline (speedup 1.0000x reference)
#include <cuda_runtime.h>

#define TX 128
#define TY 16
#define NTHREADS 256
#define SMW 136            // mosaick tile width: halo 4 each side (16B aligned)
#define SMH (TY + 4)       // 20
#define SDW 68             // parity-split packed diff width (34 even | 34 odd)
#define SDH (TY + 2)       // 18
#define EPS 1e-8f

// sd physical layout: logical packed index k -> (k>>1) + (k&1)*34
#define KP(k) ((((k) >> 1)) + (((k) & 1) * 34))

// Fused learnable demosaick.
//  sm column i  <-> global x = bx0 + i - 4   (parity(x) == parity(i))
//  sm row    r  <-> global y = by0 + r - 2
//  sd row    j  <-> global y = by0 + j - 1
//  sd[j][KP(k)] = (m - g_interp) at non-green site i = 2*k + pr, pr = 1-(y&1)
__global__ __launch_bounds__(NTHREADS) void demosaick_kernel(
    const float* __restrict__ m,
    const float* __restrict__ gfilt,
    const float* __restrict__ grad_filt,
    float* __restrict__ out,
    int H, int W)
{
    __shared__ __align__(16) float sm[SMH][SMW];
    __shared__ __align__(16) float sd[SDH][SDW];

    const int bx0 = blockIdx.x * TX;
    const int by0 = blockIdx.y * TY;
    const int b   = blockIdx.z;
    const float* __restrict__ mb = m + (size_t)b * H * W;
    const int tid = threadIdx.x;

    const float gf0 = gfilt[0], gf1 = gfilt[1], gf2 = gfilt[2];
    const float r0  = grad_filt[0], r1 = grad_filt[1], r2 = grad_filt[2];

    // ---------------- tile load (edge-clamped == jnp.pad mode='edge') --------
    if ((bx0 > 0) && (bx0 + TX < W)) {
        #pragma unroll
        for (int idx = tid; idx < SMH * (SMW / 4); idx += NTHREADS) {
            int row = idx / (SMW / 4);
            int q   = idx - row * (SMW / 4);
            int gy  = min(max(by0 - 2 + row, 0), H - 1);
            float4 v = *reinterpret_cast<const float4*>(
                &mb[(size_t)gy * W + (bx0 - 4 + 4 * q)]);
            *reinterpret_cast<float4*>(&sm[row][4 * q]) = v;
        }
    } else {
        for (int idx = tid; idx < SMH * SMW; idx += NTHREADS) {
            int row = idx / SMW;
            int i   = idx - row * SMW;
            int gy  = min(max(by0 - 2 + row, 0), H - 1);
            int gx  = min(max(bx0 - 4 + i, 0), W - 1);
            sm[row][i] = mb[(size_t)gy * W + gx];
        }
    }
    __syncthreads();

    // ---------------- diff fill: sd = m - g_interp at non-green sites --------
    {
        const int NP = SDH * 66;
        for (int idx = tid; idx < NP; idx += NTHREADS) {
            int j  = idx / 66;
            int kk = idx - j * 66 + 1;         // k in [1,66]
            int y  = by0 - 1 + j;
            int pr = 1 - (y & 1);              // non-green column parity
            int i  = 2 * kk + pr;              // i in [2,134]

            float c  = sm[j + 1][i];
            float xl = sm[j + 1][i - 1];
            float xr = sm[j + 1][i + 1];
            float yu = sm[j][i];
            float yd = sm[j + 2][i];

            float gh = gf0 * xl + gf1 * c + gf2 * xr;
            float gv = gf0 * yu + gf1 * c + gf2 * yd;
            float dx = r0 * xl + r1 * c + r2 * xr;
            float dy = r0 * yu + r1 * c + r2 * yd;

            float adx = fabsf(dx), ady = fabsf(dy);
            float w   = __fdividef(ady, adx + ady + EPS);
            float gi  = w * gh + (1.0f - w) * gv;
            sd[j][KP(kk)] = c - gi;
        }
    }
    __syncthreads();

    // ---------------- chroma + output: 4 px/thread, conflict-free sd reads ---
    const size_t img = (size_t)H * W;
    float* __restrict__ outr = out + (size_t)(b * 3 + 0) * img;
    float* __restrict__ outg = out + (size_t)(b * 3 + 1) * img;
    float* __restrict__ outb = out + (size_t)(b * 3 + 2) * img;

    const int t   = tid & 31;          // 32 threads across x, 4 px each
    const int tyg = tid >> 5;          // 8 row groups
    const int x0  = bx0 + 4 * t;
    const int cb  = 4 * t + 4;         // sm column of pixel x0

    #pragma unroll
    for (int rr = 0; rr < 2; ++rr) {
        const int ty = tyg + 8 * rr;
        const int y  = by0 + ty;
        const size_t o = (size_t)y * W + x0;

        const bool fast = (y > 0) & (y < H - 1) & (x0 > 0) & (x0 < W - 4);
        if (fast) {
            float4 m4 = *reinterpret_cast<const float4*>(&sm[ty + 2][cb]);
            const float* su = sd[ty];
            const float* so = sd[ty + 1];
            const float* sdn = sd[ty + 2];
            float4 G, R, Bv;
            if ((y & 1) == 0) {
                // classes: G R G R (own row pr=1 -> odd k; up/down pr=0 -> even k)
                float dA  = so[t + 34];      // i = cb-1
                float dB  = so[t + 1];       // i = cb+1
                float dC  = so[t + 35];      // i = cb+3
                float du0 = su[t + 1];       // i = cb
                float du2 = su[t + 35];      // i = cb+2
                float du4 = su[t + 2];       // i = cb+4
                float dd0 = sdn[t + 1];
                float dd2 = sdn[t + 35];
                float dd4 = sdn[t + 2];
                G.x = m4.x;            G.y = m4.y - dB;
                G.z = m4.z;            G.w = m4.w - dC;
                R.x = m4.x + 0.5f * (dA + dB);
                R.y = m4.y;
                R.z = m4.z + 0.5f * (dB + dC);
                R.w = m4.w;
                Bv.x = m4.x + 0.5f  * (du0 + dd0);
                Bv.y = G.y  + 0.25f * (du0 + du2 + dd0 + dd2);
                Bv.z = m4.z + 0.5f  * (du2 + dd2);
                Bv.w = G.w  + 0.25f * (du2 + du4 + dd2 + dd4);
            } else {
                // classes: B G B G (own row pr=0 -> even k; up/down pr=1 -> odd k)
                float d0  = so[t + 1];       // i = cb
                float d2  = so[t + 35];      // i = cb+2
                float d4  = so[t + 2];       // i = cb+4
                float dua = su[t + 34];      // i = cb-1
                float dub = su[t + 1];       // i = cb+1
                float duc = su[t + 35];      // i = cb+3
                float dda = sdn[t + 34];
                float ddb = sdn[t + 1];
                float ddc = sdn[t + 35];
                G.x = m4.x - d0;       G.y = m4.y;
                G.z = m4.z - d2;       G.w = m4.w;
                Bv.x = m4.x;
                Bv.y = m4.y + 0.5f * (d0 + d2);
                Bv.z = m4.z;
                Bv.w = m4.w + 0.5f * (d2 + d4);
                R.x = G.x  + 0.25f * (dua + dub + dda + ddb);
                R.y = m4.y + 0.5f  * (dub + ddb);
                R.z = G.z  + 0.25f * (dub + duc + ddb + ddc);
                R.w = m4.w + 0.5f  * (duc + ddc);
            }
            *reinterpret_cast<float4*>(&outr[o]) = R;
            *reinterpret_cast<float4*>(&outg[o]) = G;
            *reinterpret_cast<float4*>(&outb[o]) = Bv;
        } else {
            // generic bounds-checked path (boundary ring only)
            #pragma unroll
            for (int kk = 0; kk < 4; ++kk) {
                int x  = x0 + kk;
                int ii = cb + kk;
                float mv = sm[ty + 2][ii];
                bool isg = ((x & 1) == (y & 1));
                int pro  = 1 - (y & 1);
                int kown = (ii - pro) >> 1;
                float g  = isg ? mv : mv - sd[ty + 1][KP(kown)];

                float nr = 0.f, dr = 0.f, nb = 0.f, db = 0.f;
                #pragma unroll
                for (int dyy = -1; dyy <= 1; ++dyy) {
                    #pragma unroll
                    for (int dxx = -1; dxx <= 1; ++dxx) {
                        int yy = y + dyy, xx = x + dxx;
                        if (yy < 0 || yy >= H || xx < 0 || xx >= W) continue;
                        bool isr = ((yy & 1) == 0) & ((xx & 1) == 1);
                        bool isb = ((yy & 1) == 1) & ((xx & 1) == 0);
                        if (isr | isb) {
                            float kw = 0.25f * (float)((2 - abs(dyy)) * (2 - abs(dxx)));
                            int prr  = 1 - (yy & 1);
                            int kq   = (ii + dxx - prr) >> 1;
                            float d  = sd[ty + 1 + dyy][KP(kq)];
                            if (isr) { nr += kw * d; dr += kw; }
                            else     { nb += kw * d; db += kw; }
                        }
                    }
                }
                outr[o + kk] = g + nr / (dr + EPS);
                outg[o + kk] = g;
                outb[o + kk] = g + nb / (db + EPS);
            }
        }
    }
}

extern "C" void kernel_launch(void* const* d_in, const int* in_sizes, int n_in,
                              void* d_out, int out_size)
{
    const float* m         = (const float*)d_in[0];
    const float* gfilt     = (const float*)d_in[1];
    const float* grad_filt = (const float*)d_in[2];
    float* out             = (float*)d_out;

    const int H = 1024, W = 1024;
    const int B = in_sizes[0] / (H * W);

    dim3 block(NTHREADS);
    dim3 grid(W / TX, H / TY, B);
    demosaick_kernel<<<grid, block>>>(m, gfilt, grad_filt, out, H, W);
}

// round 5
// speedup vs baseline: 1.1038x; 1.1038x over previous
#include <cuda_runtime.h>

#define TX 128
#define TY 16
#define NTHREADS 256
#define SMW 136            // mosaick tile width: halo 4 each side (16B aligned)
#define SMH (TY + 4)       // 20
#define SDW 68             // packed diff width
#define SDH (TY + 2)       // 18
#define EPS 1e-8f

// Fused learnable demosaick.
//  sm column i  <-> global x = bx0 + i - 4   (parity(x) == parity(i))
//  sm row    r  <-> global y = by0 + r - 2
//  sd row    j  <-> global y = by0 + j - 1
//  sd[j][k] = (m - g_interp) at non-green site i = 2*k + pr, pr = 1 - (y&1)
__global__ __launch_bounds__(NTHREADS) void demosaick_kernel(
    const float* __restrict__ m,
    const float* __restrict__ gfilt,
    const float* __restrict__ grad_filt,
    float* __restrict__ out,
    int H, int W)
{
    __shared__ __align__(16) float sm[SMH][SMW];
    __shared__ __align__(16) float sd[SDH][SDW];

    const int bx0 = blockIdx.x * TX;
    const int by0 = blockIdx.y * TY;
    const int b   = blockIdx.z;
    const float* __restrict__ mb = m + (size_t)b * H * W;
    const int tid = threadIdx.x;

    const float gf0 = gfilt[0], gf1 = gfilt[1], gf2 = gfilt[2];
    const float r0  = grad_filt[0], r1 = grad_filt[1], r2 = grad_filt[2];

    // ---------------- tile load (edge-clamped == jnp.pad mode='edge') --------
    if ((bx0 > 0) && (bx0 + TX < W)) {
        #pragma unroll
        for (int idx = tid; idx < SMH * (SMW / 4); idx += NTHREADS) {
            int row = idx / (SMW / 4);
            int q   = idx - row * (SMW / 4);
            int gy  = min(max(by0 - 2 + row, 0), H - 1);
            float4 v = *reinterpret_cast<const float4*>(
                &mb[(size_t)gy * W + (bx0 - 4 + 4 * q)]);
            *reinterpret_cast<float4*>(&sm[row][4 * q]) = v;
        }
    } else {
        for (int idx = tid; idx < SMH * SMW; idx += NTHREADS) {
            int row = idx / SMW;
            int i   = idx - row * SMW;
            int gy  = min(max(by0 - 2 + row, 0), H - 1);
            int gx  = min(max(bx0 - 4 + i, 0), W - 1);
            sm[row][i] = mb[(size_t)gy * W + gx];
        }
    }
    __syncthreads();

    // ---------------- diff fill: sd = m - g_interp at non-green sites --------
    {
        const int NP = SDH * 66;
        for (int idx = tid; idx < NP; idx += NTHREADS) {
            int j  = idx / 66;
            int kk = idx - j * 66 + 1;         // k in [1,66]
            int y  = by0 - 1 + j;
            int pr = 1 - (y & 1);              // non-green column parity
            int i  = 2 * kk + pr;              // i in [2,134]

            float c  = sm[j + 1][i];
            float xl = sm[j + 1][i - 1];
            float xr = sm[j + 1][i + 1];
            float yu = sm[j][i];
            float yd = sm[j + 2][i];

            float gh = gf0 * xl + gf1 * c + gf2 * xr;
            float gv = gf0 * yu + gf1 * c + gf2 * yd;
            float dx = r0 * xl + r1 * c + r2 * xr;
            float dy = r0 * yu + r1 * c + r2 * yd;

            float adx = fabsf(dx), ady = fabsf(dy);
            float w   = __fdividef(ady, adx + ady + EPS);
            float gi  = w * gh + (1.0f - w) * gv;
            sd[j][kk] = c - gi;
        }
    }
    __syncthreads();

    // ------- chroma + output: vertical row pair (even+odd) per iteration -----
    const size_t img = (size_t)H * W;
    float* __restrict__ outr = out + (size_t)(b * 3 + 0) * img;
    float* __restrict__ outg = out + (size_t)(b * 3 + 1) * img;
    float* __restrict__ outb = out + (size_t)(b * 3 + 2) * img;

    const int c   = tid & 63;          // pair column
    const int grp = tid >> 6;          // 4 groups
    const int x0  = bx0 + 2 * c;
    const int cb  = 2 * c + 4;         // sm column of pixel x0

    #pragma unroll
    for (int rr = 0; rr < 2; ++rr) {
        const int ty = 2 * (grp + 4 * rr);    // even: 0,2,..,14
        const int y  = by0 + ty;              // even row (G R ...)
        const size_t o = (size_t)y * W + x0;

        const bool fast = (y > 0) & (y + 1 < H - 1) & (x0 > 0) & (x0 < W - 2);
        if (fast) {
            float2 m2t = *reinterpret_cast<const float2*>(&sm[ty + 2][cb]);
            float2 m2b = *reinterpret_cast<const float2*>(&sm[ty + 3][cb]);

            // shared diffs (8 reads serve 4 pixels)
            float du0 = sd[ty][c + 2];         // row y-1 (odd, pr=0), i=cb
            float du2 = sd[ty][c + 3];         // i=cb+2
            float dLo = sd[ty + 1][c + 1];     // row y (even, pr=1), i=cb-1
            float dCo = sd[ty + 1][c + 2];     // i=cb+1
            float dd0 = sd[ty + 2][c + 2];     // row y+1 (odd, pr=0), i=cb
            float dd2 = sd[ty + 2][c + 3];     // i=cb+2
            float dda = sd[ty + 3][c + 1];     // row y+2 (even, pr=1), i=cb-1
            float ddb = sd[ty + 3][c + 2];     // i=cb+1

            // ---- top row (even): classes G R ----
            float2 Gt, Rt, Bt;
            Gt.x = m2t.x;
            Gt.y = m2t.y - dCo;
            Rt.x = Gt.x + 0.5f * (dLo + dCo);
            Rt.y = m2t.y;
            Bt.x = Gt.x + 0.5f  * (du0 + dd0);
            Bt.y = Gt.y + 0.25f * (du0 + du2 + dd0 + dd2);

            // ---- bottom row (odd): classes B G ----
            float2 Gb, Rb, Bb;
            Gb.x = m2b.x - dd0;
            Gb.y = m2b.y;
            Bb.x = m2b.x;
            Bb.y = Gb.y + 0.5f * (dd0 + dd2);
            Rb.x = Gb.x + 0.25f * (dLo + dCo + dda + ddb);
            Rb.y = Gb.y + 0.5f  * (dCo + ddb);

            *reinterpret_cast<float2*>(&outr[o])     = Rt;
            *reinterpret_cast<float2*>(&outg[o])     = Gt;
            *reinterpret_cast<float2*>(&outb[o])     = Bt;
            *reinterpret_cast<float2*>(&outr[o + W]) = Rb;
            *reinterpret_cast<float2*>(&outg[o + W]) = Gb;
            *reinterpret_cast<float2*>(&outb[o + W]) = Bb;
        } else {
            // generic bounds-checked path (boundary ring only)
            #pragma unroll
            for (int ry = 0; ry < 2; ++ry) {
                const int yr = y + ry;
                const size_t orow = o + (size_t)ry * W;
                #pragma unroll
                for (int kk = 0; kk < 2; ++kk) {
                    int x  = x0 + kk;
                    int ii = cb + kk;
                    float mv = sm[ty + 2 + ry][ii];
                    bool isg = ((x & 1) == (yr & 1));
                    int pro  = 1 - (yr & 1);
                    float g  = isg ? mv : mv - sd[ty + 1 + ry][(ii - pro) >> 1];

                    float nr = 0.f, dr = 0.f, nb = 0.f, db = 0.f;
                    #pragma unroll
                    for (int dyy = -1; dyy <= 1; ++dyy) {
                        #pragma unroll
                        for (int dxx = -1; dxx <= 1; ++dxx) {
                            int yy = yr + dyy, xx = x + dxx;
                            if (yy < 0 || yy >= H || xx < 0 || xx >= W) continue;
                            bool isr = ((yy & 1) == 0) & ((xx & 1) == 1);
                            bool isb = ((yy & 1) == 1) & ((xx & 1) == 0);
                            if (isr | isb) {
                                float kw = 0.25f * (float)((2 - abs(dyy)) * (2 - abs(dxx)));
                                int prr  = 1 - (yy & 1);
                                float d  = sd[ty + 1 + ry + dyy][(ii + dxx - prr) >> 1];
                                if (isr) { nr += kw * d; dr += kw; }
                                else     { nb += kw * d; db += kw; }
                            }
                        }
                    }
                    outr[orow + kk] = g + nr / (dr + EPS);
                    outg[orow + kk] = g;
                    outb[orow + kk] = g + nb / (db + EPS);
                }
            }
        }
    }
}

extern "C" void kernel_launch(void* const* d_in, const int* in_sizes, int n_in,
                              void* d_out, int out_size)
{
    const float* m         = (const float*)d_in[0];
    const float* gfilt     = (const float*)d_in[1];
    const float* grad_filt = (const float*)d_in[2];
    float* out             = (float*)d_out;

    const int H = 1024, W = 1024;
    const int B = in_sizes[0] / (H * W);

    dim3 block(NTHREADS);
    dim3 grid(W / TX, H / TY, B);
    demosaick_kernel<<<grid, block>>>(m, gfilt, grad_filt, out, H, W);
}